// round 16
// baseline (speedup 1.0000x reference)
#include <cuda_runtime.h>
#include <cuda_fp16.h>
#include <cstdint>
#include <math.h>

#define NB 2
#define NH 16
#define HD 64
#define SQ 2048
#define EM 1024

// Scratch (device globals; runtime allocation is forbidden)
__device__ __align__(256) __half g_Xh[(size_t)NB*SQ*EM];
__device__ __align__(256) __half g_Wh[(size_t)4*EM*EM];   // Wq,Wk,Wv,Wo fp16
__device__ __align__(256) __half g_Qh[(size_t)NB*NH*SQ*HD];
__device__ __align__(256) __half g_Kh[(size_t)NB*NH*SQ*HD];
__device__ __align__(256) __half g_Vh[(size_t)NB*NH*SQ*HD];
__device__ __align__(256) __half g_Ch[(size_t)NB*SQ*EM];

// ---------------------------------------------------------------------------
__device__ __forceinline__ void mma16816(float c[4], const unsigned a[4],
                                         unsigned b0, unsigned b1)
{
    asm volatile(
        "mma.sync.aligned.m16n8k16.row.col.f32.f16.f16.f32 "
        "{%0,%1,%2,%3}, {%4,%5,%6,%7}, {%8,%9}, {%0,%1,%2,%3};\n"
        : "+f"(c[0]), "+f"(c[1]), "+f"(c[2]), "+f"(c[3])
        : "r"(a[0]), "r"(a[1]), "r"(a[2]), "r"(a[3]), "r"(b0), "r"(b1));
}
__device__ __forceinline__ unsigned packh2(float x, float y)
{
    __half2 h = __floats2half2_rn(x, y);
    return *(unsigned*)&h;
}
__device__ __forceinline__ uint32_t s2u(const void* p)
{
    return (uint32_t)__cvta_generic_to_shared(p);
}
__device__ __forceinline__ void ldsm4(unsigned r[4], uint32_t a)
{
    asm volatile("ldmatrix.sync.aligned.m8n8.x4.shared.b16 {%0,%1,%2,%3}, [%4];"
                 : "=r"(r[0]), "=r"(r[1]), "=r"(r[2]), "=r"(r[3]) : "r"(a));
}
__device__ __forceinline__ void ldsm4t(unsigned r[4], uint32_t a)
{
    asm volatile("ldmatrix.sync.aligned.m8n8.x4.trans.shared.b16 {%0,%1,%2,%3}, [%4];"
                 : "=r"(r[0]), "=r"(r[1]), "=r"(r[2]), "=r"(r[3]) : "r"(a));
}
__device__ __forceinline__ void cpa16(uint32_t d, const void* s)
{
    asm volatile("cp.async.ca.shared.global [%0], [%1], 16;" :: "r"(d), "l"(s));
}
__device__ __forceinline__ void cpa16cg(uint32_t d, const void* s)
{
    asm volatile("cp.async.cg.shared.global [%0], [%1], 16;" :: "r"(d), "l"(s));
}
__device__ __forceinline__ void cp_commit() { asm volatile("cp.async.commit_group;"); }
__device__ __forceinline__ void cp_wait_tail(bool more)
{
    if (more) asm volatile("cp.async.wait_group 1;");
    else      asm volatile("cp.async.wait_group 0;");
}
__device__ __forceinline__ void cp_wait0() { asm volatile("cp.async.wait_group 0;"); }
__device__ __forceinline__ float frcp(float x)
{
    float r;
    asm("rcp.approx.f32 %0, %1;" : "=f"(r) : "f"(x));
    return r;
}

// ---------------------------------------------------------------------------
// Fused fp32->fp16: x (2M floats) + 4 weights (1M floats each), grid-stride.
// ---------------------------------------------------------------------------
#define X_F4   ((NB*SQ*EM)/4)
#define W_F4   ((EM*EM)/4)
#define TOT_F4 (X_F4 + 4*W_F4)

__global__ void f2h_all(const float* __restrict__ x,
                        const float* __restrict__ w0, const float* __restrict__ w1,
                        const float* __restrict__ w2, const float* __restrict__ w3)
{
    __half* dstX = g_Xh;
    __half* dstW = g_Wh;
    for (int i = blockIdx.x * blockDim.x + threadIdx.x; i < TOT_F4;
         i += gridDim.x * blockDim.x) {
        const float* src; __half* dst; int off;
        if (i < X_F4) { src = x; dst = dstX; off = i; }
        else {
            int j = i - X_F4;
            int w = j / W_F4;  off = j - w * W_F4;
            src = (w == 0) ? w0 : (w == 1) ? w1 : (w == 2) ? w2 : w3;
            dst = dstW + (size_t)w * (EM * EM);
        }
        float4 v = ((const float4*)src)[off];
        ((__half2*)dst)[off*2]   = __floats2half2_rn(v.x, v.y);
        ((__half2*)dst)[off*2+1] = __floats2half2_rn(v.z, v.w);
    }
}

// ---------------------------------------------------------------------------
// Tensor-core GEMM (unchanged from R11 pass): 128x128 block, k-chunk 64,
// 2-stage cp.async.cg, one sync/iter, register-double-buffered fragments.
// ---------------------------------------------------------------------------
#define APAD 72
#define BPAD 136

__global__ __launch_bounds__(256, 2)
void gemm_tc(const __half* __restrict__ A,
             const float* __restrict__ bq, const float* __restrict__ bk,
             const float* __restrict__ bv, float* __restrict__ Cout, int qkv)
{
    extern __shared__ __half sm[];
    __half (*As)[128][APAD] = (__half(*)[128][APAD])sm;
    __half (*Bs)[64][BPAD]  = (__half(*)[64][BPAD])(sm + 2*128*APAD);

    int wsel, n0;
    if (qkv) { wsel = blockIdx.x >> 3; n0 = (blockIdx.x & 7) * 128; }
    else     { wsel = 3;               n0 = blockIdx.x * 128; }
    const int m0 = blockIdx.y * 128;
    const __half* W = g_Wh + (size_t)wsel * EM * EM;
    const float* bias = qkv ? (wsel == 0 ? bq : (wsel == 1 ? bk : bv)) : bq;

    const int tid = threadIdx.x;
    const int wid = tid >> 5, lane = tid & 31;
    const int g = lane >> 2, tig = lane & 3;
    const int wm = (wid >> 2) * 64, wn = (wid & 3) * 32;

    auto prefetch = [&](int kt, int st) {
        int k0 = kt * 64;
#pragma unroll
        for (int i = 0; i < 4; i++) {
            int c = tid + 256 * i;
            int r = c >> 3, s = (c & 7) * 8;
            cpa16cg(s2u(&As[st][r][s]), A + (size_t)(m0 + r) * EM + k0 + s);
        }
#pragma unroll
        for (int i = 0; i < 4; i++) {
            int c = tid + 256 * i;
            int r = c >> 4, s = (c & 15) * 8;
            cpa16cg(s2u(&Bs[st][r][s]), W + (size_t)(k0 + r) * EM + n0 + s);
        }
        cp_commit();
    };

    float c[4][4][4] = {};
    unsigned af[2][4][4], bf[2][2][4];

    auto loadf = [&](int st, int t, int buf) {
        const int kk = t * 16;
#pragma unroll
        for (int i = 0; i < 4; i++)
            ldsm4(af[buf][i], s2u(&As[st][wm + 16*i + (lane & 15)][kk + (lane >> 4) * 8]));
#pragma unroll
        for (int jp = 0; jp < 2; jp++)
            ldsm4t(bf[buf][jp], s2u(&Bs[st][kk + (lane & 15)][wn + jp*16 + (lane >> 4) * 8]));
    };

    prefetch(0, 0);
    const int NIT = EM / 64;   // 16
    for (int kt = 0; kt < NIT; kt++) {
        cp_wait0();
        __syncthreads();
        if (kt + 1 < NIT) prefetch(kt + 1, (kt + 1) & 1);
        const int st = kt & 1;

        loadf(st, 0, 0);
#pragma unroll
        for (int t = 0; t < 4; t++) {
            const int cur = t & 1;
            if (t < 3) loadf(st, t + 1, cur ^ 1);
#pragma unroll
            for (int i = 0; i < 4; i++)
#pragma unroll
                for (int j = 0; j < 4; j++)
                    mma16816(c[i][j], af[cur][i],
                             bf[cur][j >> 1][(j & 1) * 2],
                             bf[cur][j >> 1][(j & 1) * 2 + 1]);
        }
    }

    // ---- Epilogue: add bias in place ----
#pragma unroll
    for (int j = 0; j < 4; j++) {
        int col = n0 + wn + j * 8 + tig * 2;
        float bi0 = bias[col], bi1 = bias[col + 1];
#pragma unroll
        for (int i = 0; i < 4; i++) {
            c[i][j][0] += bi0; c[i][j][1] += bi1;
            c[i][j][2] += bi0; c[i][j][3] += bi1;
        }
    }

    // ---- Fused L2 norm for Q/K (per row within each 64-col head) ----
    if (qkv && wsel < 2) {
        float sq0[4], sq1[4];
#pragma unroll
        for (int i = 0; i < 4; i++) {
            sq0[i] = 0.0f; sq1[i] = 0.0f;
#pragma unroll
            for (int j = 0; j < 4; j++) {
                sq0[i] += c[i][j][0]*c[i][j][0] + c[i][j][1]*c[i][j][1];
                sq1[i] += c[i][j][2]*c[i][j][2] + c[i][j][3]*c[i][j][3];
            }
        }
#pragma unroll
        for (int i = 0; i < 4; i++) {
            sq0[i] += __shfl_xor_sync(0xffffffffu, sq0[i], 1);
            sq0[i] += __shfl_xor_sync(0xffffffffu, sq0[i], 2);
            sq1[i] += __shfl_xor_sync(0xffffffffu, sq1[i], 1);
            sq1[i] += __shfl_xor_sync(0xffffffffu, sq1[i], 2);
        }
        float* ss = (float*)sm;   // [8 warps][64 rows] = 2 KB, reuse tile smem
        __syncthreads();
        if (tig == 0) {
#pragma unroll
            for (int i = 0; i < 4; i++) {
                ss[wid*64 + 16*i + g]     = sq0[i];
                ss[wid*64 + 16*i + g + 8] = sq1[i];
            }
        }
        __syncthreads();
        const int pw = wid ^ 1;
#pragma unroll
        for (int i = 0; i < 4; i++) {
            float t0 = ss[wid*64 + 16*i + g]     + ss[pw*64 + 16*i + g];
            float t1 = ss[wid*64 + 16*i + g + 8] + ss[pw*64 + 16*i + g + 8];
            float s0 = 1.0f / (sqrtf(t0) + 1e-8f);
            float s1 = 1.0f / (sqrtf(t1) + 1e-8f);
#pragma unroll
            for (int j = 0; j < 4; j++) {
                c[i][j][0] *= s0; c[i][j][1] *= s0;
                c[i][j][2] *= s1; c[i][j][3] *= s1;
            }
        }
    }

    // ---- Write out ----
#pragma unroll
    for (int j = 0; j < 4; j++) {
        int col = n0 + wn + j * 8 + tig * 2;
#pragma unroll
        for (int i = 0; i < 4; i++) {
            int r0 = m0 + wm + 16 * i + g, r1 = r0 + 8;
            if (!qkv) {
                *(float2*)(Cout + (size_t)r0 * EM + col) = make_float2(c[i][j][0], c[i][j][1]);
                *(float2*)(Cout + (size_t)r1 * EM + col) = make_float2(c[i][j][2], c[i][j][3]);
            } else {
                __half* Out = wsel == 0 ? g_Qh : (wsel == 1 ? g_Kh : g_Vh);
                int hh = col >> 6, d = col & 63;
                int bb0 = r0 >> 11, s0 = r0 & 2047;
                int bb1 = r1 >> 11, s1 = r1 & 2047;
                *(__half2*)(Out + (((size_t)(bb0*NH + hh) * SQ + s0) * HD) + d) =
                    __floats2half2_rn(c[i][j][0], c[i][j][1]);
                *(__half2*)(Out + (((size_t)(bb1*NH + hh) * SQ + s1) * HD) + d) =
                    __floats2half2_rn(c[i][j][2], c[i][j][3]);
            }
        }
    }
}

// ---------------------------------------------------------------------------
// Yat attention. Block = (b, h, 128 queries), 8 warps, 2 CTAs/SM.
// K/V 64-key tiles, 3-stage cp.async, one sync per tile.
// Transform: score = u - 4.2 + 4.41/u with u = 1.1 - dot (3 instrs + RCP).
// Denominator: P @ ones via 4 extra MMAs (constant all-ones B fragment) —
// no scalar FADDs, no end-of-kernel shuffle reduction.
// ---------------------------------------------------------------------------
__global__ __launch_bounds__(256, 2)
void yat_attn2(const __half* __restrict__ Q, const __half* __restrict__ K,
               const __half* __restrict__ V, __half* __restrict__ ctx)
{
    extern __shared__ __half sm2[];
    __half (*Qs)[APAD]     = (__half(*)[APAD])sm2;                      // [128][72]
    __half (*Ks)[64][APAD] = (__half(*)[64][APAD])(sm2 + 128*APAD);     // [3][64][72]
    __half (*Vs)[64][APAD] = (__half(*)[64][APAD])(sm2 + 128*APAD + 3*64*APAD);

    const int q0 = blockIdx.x * 128;
    const int h  = blockIdx.y;
    const int bb = blockIdx.z;
    const size_t base = ((size_t)bb * NH + h) * SQ * HD;
    const int tid = threadIdx.x;
    const int wid = tid >> 5, lane = tid & 31;
    const int g = lane >> 2, tig = lane & 3;
    const int qr = wid * 16;

    auto prefetchKV = [&](int kt, int st) {
        int k0 = kt * 64;
#pragma unroll
        for (int i = 0; i < 2; i++) {
            int c = tid + 256 * i;
            int r = c >> 3, s = (c & 7) * 8;
            cpa16(s2u(&Ks[st][r][s]), K + base + (size_t)(k0 + r) * HD + s);
            cpa16(s2u(&Vs[st][r][s]), V + base + (size_t)(k0 + r) * HD + s);
        }
        cp_commit();
    };

    prefetchKV(0, 0);
    prefetchKV(1, 1);

#pragma unroll
    for (int i = 0; i < 4; i++) {
        int c = tid + 256 * i;
        int r = c >> 3, s = (c & 7) * 8;
        *(uint4*)&Qs[r][s] = *(const uint4*)(Q + base + (size_t)(q0 + r) * HD + s);
    }
    __syncthreads();

    unsigned qa[4][4];
#pragma unroll
    for (int t = 0; t < 4; t++)
        ldsm4(qa[t], s2u(&Qs[qr + (lane & 15)][t*16 + (lane >> 4) * 8]));

    float o[8][4] = {};
    float dacc[4] = {};
    const unsigned ONES2 = 0x3C003C00u;   // half2(1.0, 1.0)

    const int NT = SQ / 64;
    for (int kt = 0; kt < NT; kt++) {
        cp_wait_tail(kt + 1 < NT);
        __syncthreads();
        if (kt + 2 < NT) prefetchKV(kt + 2, (kt + 2) % 3);
        const int st = kt % 3;

        // QK^T: 16 q x 64 keys x 64 d
        float sc[8][4] = {};
#pragma unroll
        for (int t = 0; t < 4; t++) {
            const int kk = t * 16;
#pragma unroll
            for (int jp = 0; jp < 4; jp++) {
                unsigned kb[4];
                ldsm4(kb, s2u(&Ks[st][jp*16 + ((lane >> 4) << 3) + (lane & 7)]
                                       [kk + ((lane >> 3) & 1) * 8]));
                mma16816(sc[jp*2],     qa[t], kb[0], kb[1]);
                mma16816(sc[jp*2 + 1], qa[t], kb[2], kb[3]);
            }
        }

        // Yat transform: (1+d)^2/(1.1-d) = u - 4.2 + 4.41/u,  u = 1.1-d
#pragma unroll
        for (int j = 0; j < 8; j++) {
#pragma unroll
            for (int r = 0; r < 4; r++) {
                float u = 1.1f - sc[j][r];
                sc[j][r] = fmaf(4.41f, frcp(u), u - 4.2f);
            }
        }

        // P fp16 A-fragments from C-fragment registers
        unsigned pf[4][4];
#pragma unroll
        for (int t = 0; t < 4; t++) {
            pf[t][0] = packh2(sc[2*t][0],   sc[2*t][1]);
            pf[t][1] = packh2(sc[2*t][2],   sc[2*t][3]);
            pf[t][2] = packh2(sc[2*t+1][0], sc[2*t+1][1]);
            pf[t][3] = packh2(sc[2*t+1][2], sc[2*t+1][3]);
        }

        // Denominator: P @ ones (full k-sum lands in every lane's C frag)
#pragma unroll
        for (int t = 0; t < 4; t++)
            mma16816(dacc, pf[t], ONES2, ONES2);

        // P @ V: 16 q x 64 d x 64 keys
#pragma unroll
        for (int t = 0; t < 4; t++) {
            const int kk = t * 16;
#pragma unroll
            for (int jp = 0; jp < 4; jp++) {
                unsigned vb[4];
                ldsm4t(vb, s2u(&Vs[st][kk + ((lane >> 3) & 1) * 8 + (lane & 7)]
                                        [jp*16 + (lane >> 4) * 8]));
                mma16816(o[jp*2],     pf[t], vb[0], vb[1]);
                mma16816(o[jp*2 + 1], pf[t], vb[2], vb[3]);
            }
        }
    }

    // dacc[0] = full den for row qr+g, dacc[2] = row qr+g+8 (no reduction!)
    float inv0 = 1.0f / (dacc[0] + 1e-6f);
    float inv1 = 1.0f / (dacc[2] + 1e-6f);

    const size_t obase = (size_t)bb * SQ * EM + (size_t)h * HD;
    int r0 = q0 + qr + g, r1 = r0 + 8;
#pragma unroll
    for (int j = 0; j < 8; j++) {
        int col = j * 8 + tig * 2;
        *(__half2*)(ctx + obase + (size_t)r0 * EM + col) =
            __floats2half2_rn(o[j][0] * inv0, o[j][1] * inv0);
        *(__half2*)(ctx + obase + (size_t)r1 * EM + col) =
            __floats2half2_rn(o[j][2] * inv1, o[j][3] * inv1);
    }
}

// ---------------------------------------------------------------------------
extern "C" void kernel_launch(void* const* d_in, const int* in_sizes, int n_in,
                              void* d_out, int out_size)
{
    const float* x  = (const float*)d_in[0];
    const float* Wq = (const float*)d_in[1];
    const float* bq = (const float*)d_in[2];
    const float* Wk = (const float*)d_in[3];
    const float* bk = (const float*)d_in[4];
    const float* Wv = (const float*)d_in[5];
    const float* bv = (const float*)d_in[6];
    const float* Wo = (const float*)d_in[7];
    const float* bo = (const float*)d_in[8];
    float* out = (float*)d_out;

    __half *dXh, *dCh, *dQh, *dKh, *dVh;
    cudaGetSymbolAddress((void**)&dXh, g_Xh);
    cudaGetSymbolAddress((void**)&dCh, g_Ch);
    cudaGetSymbolAddress((void**)&dQh, g_Qh);
    cudaGetSymbolAddress((void**)&dKh, g_Kh);
    cudaGetSymbolAddress((void**)&dVh, g_Vh);

    const int M = NB * SQ;

    // Single fused fp32 -> fp16 staging pass (x + all 4 weights)
    f2h_all<<<4096, 256>>>(x, Wq, Wk, Wv, Wo);

    const int gemm_smem = 2*128*APAD*2 + 2*64*BPAD*2;   // 71,680 B -> 2 CTAs/SM
    cudaFuncSetAttribute(gemm_tc, cudaFuncAttributeMaxDynamicSharedMemorySize, gemm_smem);

    // Fused QKV (+ fused L2 norm on Q/K)
    gemm_tc<<<dim3(24, M / 128), 256, gemm_smem>>>(dXh, bq, bk, bv, nullptr, 1);

    const int attn_smem = (128*APAD + 6*64*APAD) * 2;   // 73,728 B -> 2 CTAs/SM
    cudaFuncSetAttribute(yat_attn2, cudaFuncAttributeMaxDynamicSharedMemorySize, attn_smem);
    yat_attn2<<<dim3(SQ / 128, NH, NB), 256, attn_smem>>>(dQh, dKh, dVh, dCh);

    // Output projection
    gemm_tc<<<dim3(8, M / 128), 256, gemm_smem>>>(dCh, bo, nullptr, nullptr, out, 0);
}